// round 5
// baseline (speedup 1.0000x reference)
#include <cuda_runtime.h>

// ---------------------------------------------------------------------------
// GCN 2-layer forward:
//   h1 = x @ W1                      [N,128]
//   a1 = A_norm @ h1 ; h1r = relu(a1 + b1)   (A_norm includes self loops)
//   h2 = h1r @ W2                    [N,16]
//   a2 = A_norm @ h2 ; out = log_softmax(a2 + b2)
// A_norm edge (s->d) weight = dinv[s]*dinv[d], dinv = rsqrt(1 + indeg_dst).
// Self-loop contribution = dinv[i]^2 * h[i], folded into the post kernels.
// NOTE: edge_index is int32 (JAX x64-disabled truncates the requested int64).
// ---------------------------------------------------------------------------

#define NMAX 50000

__device__ float g_deg [NMAX];
__device__ float g_dinv[NMAX];
__device__ __align__(16) float g_h1  [NMAX * 128];
__device__ __align__(16) float g_agg1[NMAX * 128];   // rewritten in place as relu'd hidden
__device__ __align__(16) float g_h2  [NMAX * 16];
__device__ __align__(16) float g_agg2[NMAX * 16];

// ---------------- degree / normalization ----------------------------------

__global__ void k_deg_init(int n) {
    int i = blockIdx.x * blockDim.x + threadIdx.x;
    if (i < n) g_deg[i] = 1.0f;          // self loop
}

__global__ void k_deg_count(const int* __restrict__ dst, int E) {
    int e = blockIdx.x * blockDim.x + threadIdx.x;
    if (e < E) atomicAdd(&g_deg[dst[e]], 1.0f);
}

__global__ void k_dinv(int n) {
    int i = blockIdx.x * blockDim.x + threadIdx.x;
    if (i < n) g_dinv[i] = rsqrtf(g_deg[i]);
}

// ---------------- zero scratch ---------------------------------------------

__global__ void k_zero1(int n) {
    int i = blockIdx.x * blockDim.x + threadIdx.x;
    if (i < n * 32) ((float4*)g_agg1)[i] = make_float4(0.f, 0.f, 0.f, 0.f);
}

__global__ void k_zero2(int n) {
    int i = blockIdx.x * blockDim.x + threadIdx.x;
    if (i < n * 4) ((float4*)g_agg2)[i] = make_float4(0.f, 0.f, 0.f, 0.f);
}

// ---------------- GEMM1: h1 = x @ W1  (K=256, Ncols=128) -------------------
// 64 rows x 128 cols per block, K-chunks of 64, 48KB static smem.
// Per-thread microtile 8 rows x 4 cols.

__global__ void __launch_bounds__(256) k_gemm1(const float* __restrict__ X,
                                               const float* __restrict__ W,
                                               int n) {
    __shared__ float Xs[64][64];
    __shared__ float Ws[64][128];
    const int tid  = threadIdx.x;
    const int tcol = tid & 31;     // col group: cols 4*tcol .. +3
    const int trow = tid >> 5;     // row group: rows 8*trow .. +7
    const int row0 = blockIdx.x * 64;

    float acc[8][4];
#pragma unroll
    for (int r = 0; r < 8; r++)
        acc[r][0] = acc[r][1] = acc[r][2] = acc[r][3] = 0.f;

    for (int k0 = 0; k0 < 256; k0 += 64) {
        // stage X tile (64x64)
#pragma unroll
        for (int i = tid; i < 64 * 16; i += 256) {
            int r = i >> 4, c = (i & 15) << 2;
            int gr = row0 + r;
            float4 v = make_float4(0.f, 0.f, 0.f, 0.f);
            if (gr < n) v = *(const float4*)(X + (size_t)gr * 256 + k0 + c);
            *(float4*)&Xs[r][c] = v;
        }
        // stage W tile (64x128)
#pragma unroll
        for (int i = tid; i < 64 * 32; i += 256) {
            int r = i >> 5, c = (i & 31) << 2;
            *(float4*)&Ws[r][c] = *(const float4*)(W + (k0 + r) * 128 + c);
        }
        __syncthreads();

#pragma unroll 16
        for (int kk = 0; kk < 64; kk++) {
            float4 wv = *(float4*)&Ws[kk][tcol << 2];   // lanes consecutive: conflict-free
#pragma unroll
            for (int r = 0; r < 8; r++) {
                float xv = Xs[(trow << 3) + r][kk];     // warp-uniform: broadcast
                acc[r][0] += xv * wv.x;
                acc[r][1] += xv * wv.y;
                acc[r][2] += xv * wv.z;
                acc[r][3] += xv * wv.w;
            }
        }
        __syncthreads();
    }

#pragma unroll
    for (int r = 0; r < 8; r++) {
        int gr = row0 + (trow << 3) + r;
        if (gr < n)
            *(float4*)(g_h1 + (size_t)gr * 128 + (tcol << 2)) =
                make_float4(acc[r][0], acc[r][1], acc[r][2], acc[r][3]);
    }
}

// ---------------- scatter layer 1 (128 feats, one warp per edge) -----------

__global__ void __launch_bounds__(256) k_scatter1(const int* __restrict__ src,
                                                  const int* __restrict__ dst,
                                                  int E) {
    int w    = (blockIdx.x * 256 + threadIdx.x) >> 5;
    int lane = threadIdx.x & 31;
    if (w >= E) return;
    int s = src[w];
    int d = dst[w];
    float norm = g_dinv[s] * g_dinv[d];
    float4 v = *(const float4*)(g_h1 + (size_t)s * 128 + (lane << 2));
    float vx = v.x * norm, vy = v.y * norm, vz = v.z * norm, vw = v.w * norm;
    float* p = g_agg1 + (size_t)d * 128 + (lane << 2);
    asm volatile("red.global.add.v4.f32 [%0], {%1,%2,%3,%4};"
                 :: "l"(p), "f"(vx), "f"(vy), "f"(vz), "f"(vw)
                 : "memory");
}

// ---------------- post1: agg1 = relu(agg1 + dinv^2*h1 + b1) (in place) -----

__global__ void k_post1(const float* __restrict__ b1, int n) {
    int i = blockIdx.x * blockDim.x + threadIdx.x;
    if (i >= n * 32) return;
    int node = i >> 5, c = (i & 31) << 2;
    float di  = g_dinv[node];
    float di2 = di * di;
    float4 a = *(float4*)(g_agg1 + (size_t)node * 128 + c);
    float4 h = *(const float4*)(g_h1 + (size_t)node * 128 + c);
    float4 b = *(const float4*)(b1 + c);
    float4 o;
    o.x = fmaxf(a.x + di2 * h.x + b.x, 0.f);
    o.y = fmaxf(a.y + di2 * h.y + b.y, 0.f);
    o.z = fmaxf(a.z + di2 * h.z + b.z, 0.f);
    o.w = fmaxf(a.w + di2 * h.w + b.w, 0.f);
    *(float4*)(g_agg1 + (size_t)node * 128 + c) = o;
}

// ---------------- GEMM2: h2 = h1r @ W2  (K=128, Ncols=16) ------------------
// 64 rows per block; per-thread 1 row x 4 cols. Padded X smem avoids conflicts.

__global__ void __launch_bounds__(256) k_gemm2(const float* __restrict__ W2, int n) {
    __shared__ float Xs[64][132];     // pad 132 -> bank shift 4/row
    __shared__ float Ws[128 * 16];
    const int tid  = threadIdx.x;
    const int row0 = blockIdx.x * 64;

#pragma unroll
    for (int i = tid; i < 512; i += 256)
        ((float4*)Ws)[i] = ((const float4*)W2)[i];

#pragma unroll
    for (int i = tid; i < 64 * 32; i += 256) {
        int r = i >> 5, c = (i & 31) << 2;
        int gr = row0 + r;
        float4 v = make_float4(0.f, 0.f, 0.f, 0.f);
        if (gr < n) v = *(const float4*)(g_agg1 + (size_t)gr * 128 + c);
        *(float4*)&Xs[r][c] = v;
    }
    __syncthreads();

    const int tcol = tid & 3;      // cols 4*tcol
    const int trow = tid >> 2;     // row
    float acc[4] = {0.f, 0.f, 0.f, 0.f};
#pragma unroll 8
    for (int k = 0; k < 128; k++) {
        float  xv = Xs[trow][k];
        float4 wv = *(float4*)&Ws[k * 16 + (tcol << 2)];
        acc[0] += xv * wv.x;
        acc[1] += xv * wv.y;
        acc[2] += xv * wv.z;
        acc[3] += xv * wv.w;
    }
    int gr = row0 + trow;
    if (gr < n)
        *(float4*)(g_h2 + (size_t)gr * 16 + (tcol << 2)) =
            make_float4(acc[0], acc[1], acc[2], acc[3]);
}

// ---------------- scatter layer 2 (16 feats, 4 threads per edge) -----------

__global__ void __launch_bounds__(256) k_scatter2(const int* __restrict__ src,
                                                  const int* __restrict__ dst,
                                                  int E) {
    int g = blockIdx.x * 256 + threadIdx.x;
    int e = g >> 2, c = (g & 3) << 2;
    if (e >= E) return;
    int s = src[e];
    int d = dst[e];
    float norm = g_dinv[s] * g_dinv[d];
    float4 v = *(const float4*)(g_h2 + (size_t)s * 16 + c);
    float vx = v.x * norm, vy = v.y * norm, vz = v.z * norm, vw = v.w * norm;
    float* p = g_agg2 + (size_t)d * 16 + c;
    asm volatile("red.global.add.v4.f32 [%0], {%1,%2,%3,%4};"
                 :: "l"(p), "f"(vx), "f"(vy), "f"(vz), "f"(vw)
                 : "memory");
}

// ---------------- final: out = log_softmax(agg2 + dinv^2*h2 + b2) ----------

__global__ void k_final(const float* __restrict__ b2, float* __restrict__ out, int n) {
    int i = blockIdx.x * blockDim.x + threadIdx.x;
    if (i >= n) return;
    float di  = g_dinv[i];
    float di2 = di * di;
    float v[16];
#pragma unroll
    for (int j = 0; j < 4; j++) {
        float4 a = *(const float4*)(g_agg2 + (size_t)i * 16 + j * 4);
        float4 h = *(const float4*)(g_h2  + (size_t)i * 16 + j * 4);
        float4 b = *(const float4*)(b2 + j * 4);
        v[j * 4 + 0] = a.x + di2 * h.x + b.x;
        v[j * 4 + 1] = a.y + di2 * h.y + b.y;
        v[j * 4 + 2] = a.z + di2 * h.z + b.z;
        v[j * 4 + 3] = a.w + di2 * h.w + b.w;
    }
    float m = v[0];
#pragma unroll
    for (int j = 1; j < 16; j++) m = fmaxf(m, v[j]);
    float ssum = 0.f;
#pragma unroll
    for (int j = 0; j < 16; j++) ssum += expf(v[j] - m);
    float lse = m + logf(ssum);
#pragma unroll
    for (int j = 0; j < 16; j++) out[i * 16 + j] = v[j] - lse;
}

// ---------------------------------------------------------------------------

extern "C" void kernel_launch(void* const* d_in, const int* in_sizes, int n_in,
                              void* d_out, int out_size) {
    const float* x  = (const float*)d_in[0];
    const int*   ei = (const int*)d_in[1];          // int32: JAX truncates int64
    const float* W1 = (const float*)d_in[2];
    const float* b1 = (const float*)d_in[3];
    const float* W2 = (const float*)d_in[4];
    const float* b2 = (const float*)d_in[5];
    float*       out = (float*)d_out;

    const int n = in_sizes[0] / 256;
    const int E = in_sizes[1] / 2;
    const int* src = ei;
    const int* dst = ei + E;

    const int T = 256;
    dim3 b(T);

    // normalization coefficients
    k_deg_init<<<(n + T - 1) / T, b>>>(n);
    k_deg_count<<<(E + T - 1) / T, b>>>(dst, E);
    k_dinv<<<(n + T - 1) / T, b>>>(n);

    // layer 1
    k_zero1<<<(n * 32 + T - 1) / T, b>>>(n);
    k_gemm1<<<(n + 63) / 64, b>>>(x, W1, n);
    k_scatter1<<<(E * 32 + T - 1) / T, b>>>(src, dst, E);
    k_post1<<<(n * 32 + T - 1) / T, b>>>(b1, n);

    // layer 2
    k_zero2<<<(n * 4 + T - 1) / T, b>>>(n);
    k_gemm2<<<(n + 63) / 64, b>>>(W2, n);
    k_scatter2<<<(E * 4 + T - 1) / T, b>>>(src, dst, E);
    k_final<<<(n + T - 1) / T, b>>>(b2, out, n);
}

// round 6
// speedup vs baseline: 1.3145x; 1.3145x over previous
#include <cuda_runtime.h>

// ---------------------------------------------------------------------------
// GCN 2-layer forward with CSR-ized aggregation + f32x2 packed GEMM1.
//   h1 = x @ W1                              [N,128]   (FFMA2 packed GEMM)
//   hid = relu(A_norm @ h1 + b1)             [N,128]   (CSR gather, fused)
//   h2 = hid @ W2                            [N,16]
//   out = log_softmax(A_norm @ h2 + b2)      [N,16]    (CSR gather, fused)
// A_norm edge (s->d) weight = dinv[s]*dinv[d], dinv = rsqrt(1+indeg_dst).
// Self-loop handled analytically as dinv[i]^2 * h[i] inside the gathers.
// edge_index is int32 (JAX x64-disabled truncates the requested int64).
// ---------------------------------------------------------------------------

#define NMAX 50000
#define EMAX 800000
typedef unsigned long long ull;

__device__ int   g_indeg [NMAX];
__device__ int   g_cursor[NMAX];
__device__ int   g_rowptr[NMAX + 1];
__device__ int   g_scan  [NMAX];
__device__ int   g_bsum  [256];
__device__ int   g_boff  [256];
__device__ float g_dinv  [NMAX];
__device__ __align__(16) ull   g_emeta[EMAX];        // hi: norm bits, lo: src
__device__ __align__(16) float g_h1   [NMAX * 128];
__device__ __align__(16) float g_hid  [NMAX * 128];
__device__ __align__(16) float g_h2   [NMAX * 16];

// ---------------- f32x2 helpers --------------------------------------------

__device__ __forceinline__ void fma2(ull& acc, ull a, ull b) {
    asm("fma.rn.f32x2 %0, %1, %2, %0;" : "+l"(acc) : "l"(a), "l"(b));
}
__device__ __forceinline__ ull dup2(float w) {
    ull d; unsigned u = __float_as_uint(w);
    asm("mov.b64 %0, {%1, %1};" : "=l"(d) : "r"(u));
    return d;
}
__device__ __forceinline__ float f2lo(ull v) { return __uint_as_float((unsigned)v); }
__device__ __forceinline__ float f2hi(ull v) { return __uint_as_float((unsigned)(v >> 32)); }

// ---------------- CSR build ------------------------------------------------

__global__ void k_init(int n) {
    int i = blockIdx.x * blockDim.x + threadIdx.x;
    if (i < n) { g_indeg[i] = 0; g_cursor[i] = 0; }
}

__global__ void k_deg_count(const int* __restrict__ dst, int E) {
    int e = blockIdx.x * blockDim.x + threadIdx.x;
    if (e < E) atomicAdd(&g_indeg[dst[e]], 1);
}

__global__ void k_dinv(int n) {
    int i = blockIdx.x * blockDim.x + threadIdx.x;
    if (i < n) g_dinv[i] = rsqrtf((float)(g_indeg[i] + 1));
}

// inclusive scan within 256-blocks
__global__ void k_scan1(int n) {
    __shared__ int sh[256];
    int t = threadIdx.x, i = blockIdx.x * 256 + t;
    int v = (i < n) ? g_indeg[i] : 0;
    sh[t] = v;
    __syncthreads();
#pragma unroll
    for (int off = 1; off < 256; off <<= 1) {
        int add = (t >= off) ? sh[t - off] : 0;
        __syncthreads();
        sh[t] += add;
        __syncthreads();
    }
    if (i < n) g_scan[i] = sh[t];
    if (t == 255) g_bsum[blockIdx.x] = sh[255];
}

// exclusive scan of block totals (single block; nb <= 256)
__global__ void k_scan2(int nb) {
    __shared__ int sh[256];
    int t = threadIdx.x;
    int v = (t < nb) ? g_bsum[t] : 0;
    sh[t] = v;
    __syncthreads();
#pragma unroll
    for (int off = 1; off < 256; off <<= 1) {
        int add = (t >= off) ? sh[t - off] : 0;
        __syncthreads();
        sh[t] += add;
        __syncthreads();
    }
    g_boff[t] = sh[t] - v;   // exclusive
}

__global__ void k_scan3(int n) {
    int i = blockIdx.x * blockDim.x + threadIdx.x;
    if (i >= n) return;
    int off = g_boff[i >> 8];
    g_rowptr[i] = g_scan[i] - g_indeg[i] + off;     // exclusive
    if (i == n - 1) g_rowptr[n] = g_scan[i] + off;  // == E
}

__global__ void k_fill(const int* __restrict__ src, const int* __restrict__ dst, int E) {
    int e = blockIdx.x * blockDim.x + threadIdx.x;
    if (e >= E) return;
    int s = src[e], d = dst[e];
    int pos = g_rowptr[d] + atomicAdd(&g_cursor[d], 1);
    float nm = g_dinv[s] * g_dinv[d];
    g_emeta[pos] = ((ull)__float_as_uint(nm) << 32) | (unsigned)s;
}

// ---------------- GEMM1: h1 = x @ W1  (K=256, 128 cols) --------------------
// 64 rows x 128 cols per block. X tile stored TRANSPOSED so a row-pair is a
// packed f32x2 LDS.64; inner loop = 16 FFMA2 (fma.rn.f32x2) per k.

__global__ void __launch_bounds__(256) k_gemm1(const float* __restrict__ X,
                                               const float* __restrict__ W,
                                               int n) {
    __shared__ float XsT[64][64];    // [k][row]
    __shared__ float Ws [64][128];   // [k][col]
    const int tid  = threadIdx.x;
    const int tcol = tid & 31;       // cols 4*tcol..+3
    const int trow = tid >> 5;       // rows 8*trow..+7
    const int row0 = blockIdx.x * 64;
    const int rbase = trow << 3;

    ull acc[4][4];                   // [rowpair][col], f32x2 packs rows (2rp, 2rp+1)
#pragma unroll
    for (int rp = 0; rp < 4; rp++)
#pragma unroll
        for (int c = 0; c < 4; c++) acc[rp][c] = 0ull;

    for (int k0 = 0; k0 < 256; k0 += 64) {
        // stage X transposed: lane-major rows -> conflict-free STS
#pragma unroll
        for (int i = tid; i < 1024; i += 256) {
            int r = i & 63, c = (i >> 6) << 2;
            int gr = row0 + r;
            float4 v = make_float4(0.f, 0.f, 0.f, 0.f);
            if (gr < n) v = *(const float4*)(X + (size_t)gr * 256 + k0 + c);
            XsT[c + 0][r] = v.x;
            XsT[c + 1][r] = v.y;
            XsT[c + 2][r] = v.z;
            XsT[c + 3][r] = v.w;
        }
#pragma unroll
        for (int i = tid; i < 2048; i += 256) {
            int r = i >> 5, c = (i & 31) << 2;
            *(float4*)&Ws[r][c] = *(const float4*)(W + (k0 + r) * 128 + c);
        }
        __syncthreads();

#pragma unroll 8
        for (int kk = 0; kk < 64; kk++) {
            float4 wq = *(float4*)&Ws[kk][tcol << 2];       // per-lane, conflict-free
            ull wd0 = dup2(wq.x), wd1 = dup2(wq.y), wd2 = dup2(wq.z), wd3 = dup2(wq.w);
            ull x0 = *(const ull*)&XsT[kk][rbase + 0];      // warp-uniform broadcast
            ull x1 = *(const ull*)&XsT[kk][rbase + 2];
            ull x2 = *(const ull*)&XsT[kk][rbase + 4];
            ull x3 = *(const ull*)&XsT[kk][rbase + 6];
            fma2(acc[0][0], x0, wd0); fma2(acc[0][1], x0, wd1);
            fma2(acc[0][2], x0, wd2); fma2(acc[0][3], x0, wd3);
            fma2(acc[1][0], x1, wd0); fma2(acc[1][1], x1, wd1);
            fma2(acc[1][2], x1, wd2); fma2(acc[1][3], x1, wd3);
            fma2(acc[2][0], x2, wd0); fma2(acc[2][1], x2, wd1);
            fma2(acc[2][2], x2, wd2); fma2(acc[2][3], x2, wd3);
            fma2(acc[3][0], x3, wd0); fma2(acc[3][1], x3, wd1);
            fma2(acc[3][2], x3, wd2); fma2(acc[3][3], x3, wd3);
        }
        __syncthreads();
    }

#pragma unroll
    for (int rp = 0; rp < 4; rp++) {
        int gr = row0 + rbase + rp * 2;
        if (gr < n) {
            float4 o0 = make_float4(f2lo(acc[rp][0]), f2lo(acc[rp][1]),
                                    f2lo(acc[rp][2]), f2lo(acc[rp][3]));
            *(float4*)(g_h1 + (size_t)gr * 128 + (tcol << 2)) = o0;
        }
        if (gr + 1 < n) {
            float4 o1 = make_float4(f2hi(acc[rp][0]), f2hi(acc[rp][1]),
                                    f2hi(acc[rp][2]), f2hi(acc[rp][3]));
            *(float4*)(g_h1 + (size_t)(gr + 1) * 128 + (tcol << 2)) = o1;
        }
    }
}

// ---------------- gather layer 1 (warp per node, fused bias+relu) ----------

__global__ void __launch_bounds__(256) k_gather1(const float* __restrict__ b1, int n) {
    int node = (blockIdx.x * 256 + threadIdx.x) >> 5;
    int lane = threadIdx.x & 31;
    if (node >= n) return;
    int c = lane << 2;

    float di  = g_dinv[node];
    float di2 = di * di;
    float4 h  = *(const float4*)(g_h1 + (size_t)node * 128 + c);
    float4 a;
    a.x = di2 * h.x; a.y = di2 * h.y; a.z = di2 * h.z; a.w = di2 * h.w;

    int beg = g_rowptr[node], end = g_rowptr[node + 1];
    for (int e = beg; e < end; e++) {
        ull  m  = g_emeta[e];                 // broadcast across warp
        int  s  = (int)(unsigned)m;
        float nm = __uint_as_float((unsigned)(m >> 32));
        float4 v = *(const float4*)(g_h1 + (size_t)s * 128 + c);
        a.x += nm * v.x; a.y += nm * v.y; a.z += nm * v.z; a.w += nm * v.w;
    }
    float4 b = *(const float4*)(b1 + c);
    float4 o;
    o.x = fmaxf(a.x + b.x, 0.f);
    o.y = fmaxf(a.y + b.y, 0.f);
    o.z = fmaxf(a.z + b.z, 0.f);
    o.w = fmaxf(a.w + b.w, 0.f);
    *(float4*)(g_hid + (size_t)node * 128 + c) = o;
}

// ---------------- GEMM2: h2 = hid @ W2  (K=128, 16 cols) -------------------

__global__ void __launch_bounds__(256) k_gemm2(const float* __restrict__ W2, int n) {
    __shared__ float Xs[64][132];
    __shared__ float Ws[128 * 16];
    const int tid  = threadIdx.x;
    const int row0 = blockIdx.x * 64;

#pragma unroll
    for (int i = tid; i < 512; i += 256)
        ((float4*)Ws)[i] = ((const float4*)W2)[i];

#pragma unroll
    for (int i = tid; i < 64 * 32; i += 256) {
        int r = i >> 5, c = (i & 31) << 2;
        int gr = row0 + r;
        float4 v = make_float4(0.f, 0.f, 0.f, 0.f);
        if (gr < n) v = *(const float4*)(g_hid + (size_t)gr * 128 + c);
        *(float4*)&Xs[r][c] = v;
    }
    __syncthreads();

    const int tcol = tid & 3;
    const int trow = tid >> 2;
    float acc[4] = {0.f, 0.f, 0.f, 0.f};
#pragma unroll 8
    for (int k = 0; k < 128; k++) {
        float  xv = Xs[trow][k];
        float4 wv = *(float4*)&Ws[k * 16 + (tcol << 2)];
        acc[0] += xv * wv.x;
        acc[1] += xv * wv.y;
        acc[2] += xv * wv.z;
        acc[3] += xv * wv.w;
    }
    int gr = row0 + trow;
    if (gr < n)
        *(float4*)(g_h2 + (size_t)gr * 16 + (tcol << 2)) =
            make_float4(acc[0], acc[1], acc[2], acc[3]);
}

// ---------------- gather layer 2 + log_softmax (4 lanes per node) ----------

__global__ void __launch_bounds__(256) k_gather2(const float* __restrict__ b2,
                                                 float* __restrict__ out, int n) {
    int g    = blockIdx.x * 256 + threadIdx.x;
    int node = g >> 2, q = g & 3;
    if (node >= n) return;
    int c = q << 2;

    float di  = g_dinv[node];
    float di2 = di * di;
    float4 h  = *(const float4*)(g_h2 + (size_t)node * 16 + c);
    float4 a;
    a.x = di2 * h.x; a.y = di2 * h.y; a.z = di2 * h.z; a.w = di2 * h.w;

    int beg = g_rowptr[node], end = g_rowptr[node + 1];
    for (int e = beg; e < end; e++) {
        ull  m  = g_emeta[e];
        int  s  = (int)(unsigned)m;
        float nm = __uint_as_float((unsigned)(m >> 32));
        float4 v = *(const float4*)(g_h2 + (size_t)s * 16 + c);
        a.x += nm * v.x; a.y += nm * v.y; a.z += nm * v.z; a.w += nm * v.w;
    }
    float4 b = *(const float4*)(b2 + c);
    a.x += b.x; a.y += b.y; a.z += b.z; a.w += b.w;

    // log_softmax across 16 features spread over 4 lanes (groups of 4)
    float m4 = fmaxf(fmaxf(a.x, a.y), fmaxf(a.z, a.w));
    m4 = fmaxf(m4, __shfl_xor_sync(0xffffffffu, m4, 1, 4));
    m4 = fmaxf(m4, __shfl_xor_sync(0xffffffffu, m4, 2, 4));
    float s4 = expf(a.x - m4) + expf(a.y - m4) + expf(a.z - m4) + expf(a.w - m4);
    s4 += __shfl_xor_sync(0xffffffffu, s4, 1, 4);
    s4 += __shfl_xor_sync(0xffffffffu, s4, 2, 4);
    float lse = m4 + logf(s4);

    float4 o;
    o.x = a.x - lse; o.y = a.y - lse; o.z = a.z - lse; o.w = a.w - lse;
    *(float4*)(out + (size_t)node * 16 + c) = o;
}

// ---------------------------------------------------------------------------

extern "C" void kernel_launch(void* const* d_in, const int* in_sizes, int n_in,
                              void* d_out, int out_size) {
    const float* x  = (const float*)d_in[0];
    const int*   ei = (const int*)d_in[1];          // int32 (JAX truncation)
    const float* W1 = (const float*)d_in[2];
    const float* b1 = (const float*)d_in[3];
    const float* W2 = (const float*)d_in[4];
    const float* b2 = (const float*)d_in[5];
    float*       out = (float*)d_out;

    const int n = in_sizes[0] / 256;
    const int E = in_sizes[1] / 2;
    const int* src = ei;
    const int* dst = ei + E;
    const int nb = (n + 255) / 256;

    const int T = 256;
    dim3 b(T);

    // CSR build
    k_init     <<<(n + T - 1) / T, b>>>(n);
    k_deg_count<<<(E + T - 1) / T, b>>>(dst, E);
    k_dinv     <<<(n + T - 1) / T, b>>>(n);
    k_scan1    <<<nb, b>>>(n);
    k_scan2    <<<1, b>>>(nb);
    k_scan3    <<<nb, b>>>(n);
    k_fill     <<<(E + T - 1) / T, b>>>(src, dst, E);

    // layer 1
    k_gemm1  <<<(n + 63) / 64, b>>>(x, W1, n);
    k_gather1<<<(n * 32 + T - 1) / T, b>>>(b1, n);

    // layer 2
    k_gemm2  <<<(n + 63) / 64, b>>>(W2, n);
    k_gather2<<<(n * 4 + T - 1) / T, b>>>(b2, out, n);
}

// round 8
// speedup vs baseline: 1.4589x; 1.1099x over previous
#include <cuda_runtime.h>

// ---------------------------------------------------------------------------
// GCN 2-layer forward with CSR-ized aggregation + f32x2 packed GEMM1.
//   h1 = x @ W1                              [N,128]   (FFMA2 packed GEMM)
//   hid = relu(A_norm @ h1 + b1)             [N,128]   (CSR gather, fused)
//   h2 = hid @ W2                            [N,16]
//   out = log_softmax(A_norm @ h2 + b2)      [N,16]    (CSR gather, fused)
// A_norm edge (s->d) weight = dinv[s]*dinv[d], dinv = rsqrt(1+indeg_dst).
// Self-loop handled analytically as dinv[i]^2 * h[i] inside the gathers.
// edge_index is int32 (JAX x64-disabled truncates the requested int64).
// CSR build runs on a forked side stream, overlapped with GEMM1.
// NOTE: no tcgen05 — harness PTX target is compute_103 (no 'a' features).
// ---------------------------------------------------------------------------

#define NMAX 50000
#define EMAX 800000
typedef unsigned long long ull;

__device__ int   g_indeg [NMAX];
__device__ int   g_cursor[NMAX];
__device__ int   g_rowptr[NMAX + 1];
__device__ int   g_scan  [NMAX];
__device__ int   g_bsum  [256];
__device__ int   g_boff  [256];
__device__ float g_dinv  [NMAX];
__device__ __align__(16) ull   g_emeta[EMAX];        // hi: norm bits, lo: src
__device__ __align__(16) float g_h1   [NMAX * 128];
__device__ __align__(16) float g_hid  [NMAX * 128];
__device__ __align__(16) float g_h2   [NMAX * 16];

// ---------------- f32x2 helpers --------------------------------------------

__device__ __forceinline__ void fma2(ull& acc, ull a, ull b) {
    asm("fma.rn.f32x2 %0, %1, %2, %0;" : "+l"(acc) : "l"(a), "l"(b));
}
__device__ __forceinline__ ull dup2(float w) {
    ull d; unsigned u = __float_as_uint(w);
    asm("mov.b64 %0, {%1, %1};" : "=l"(d) : "r"(u));
    return d;
}
__device__ __forceinline__ float f2lo(ull v) { return __uint_as_float((unsigned)v); }
__device__ __forceinline__ float f2hi(ull v) { return __uint_as_float((unsigned)(v >> 32)); }

// ---------------- CSR build ------------------------------------------------

__global__ void k_init(int n) {
    int i = blockIdx.x * blockDim.x + threadIdx.x;
    if (i < n) { g_indeg[i] = 0; g_cursor[i] = 0; }
}

__global__ void k_deg_count(const int* __restrict__ dst, int E) {
    int e = blockIdx.x * blockDim.x + threadIdx.x;
    if (e < E) atomicAdd(&g_indeg[dst[e]], 1);
}

// inclusive scan within 256-blocks (warp shuffles, 2 syncs)
__global__ void k_scan1(int n) {
    __shared__ int wsum[8];
    int t = threadIdx.x, i = blockIdx.x * 256 + t;
    int lane = t & 31, w = t >> 5;
    int x = (i < n) ? g_indeg[i] : 0;
#pragma unroll
    for (int o = 1; o < 32; o <<= 1) {
        int y = __shfl_up_sync(0xffffffffu, x, o);
        if (lane >= o) x += y;
    }
    if (lane == 31) wsum[w] = x;
    __syncthreads();
    if (w == 0) {
        int s = (lane < 8) ? wsum[lane] : 0;
#pragma unroll
        for (int o = 1; o < 8; o <<= 1) {
            int y = __shfl_up_sync(0xffffffffu, s, o);
            if (lane >= o) s += y;
        }
        if (lane < 8) wsum[lane] = s;
    }
    __syncthreads();
    if (w > 0) x += wsum[w - 1];
    if (i < n) g_scan[i] = x;
    if (t == 255) g_bsum[blockIdx.x] = x;
}

// exclusive scan of block totals (single block; nb <= 256)
__global__ void k_scan2(int nb) {
    __shared__ int wsum[8];
    int t = threadIdx.x;
    int lane = t & 31, w = t >> 5;
    int v = (t < nb) ? g_bsum[t] : 0;
    int x = v;
#pragma unroll
    for (int o = 1; o < 32; o <<= 1) {
        int y = __shfl_up_sync(0xffffffffu, x, o);
        if (lane >= o) x += y;
    }
    if (lane == 31) wsum[w] = x;
    __syncthreads();
    if (w == 0) {
        int s = (lane < 8) ? wsum[lane] : 0;
#pragma unroll
        for (int o = 1; o < 8; o <<= 1) {
            int y = __shfl_up_sync(0xffffffffu, s, o);
            if (lane >= o) s += y;
        }
        if (lane < 8) wsum[lane] = s;
    }
    __syncthreads();
    if (w > 0) x += wsum[w - 1];
    g_boff[t] = x - v;   // exclusive
}

__global__ void k_scan3(int n) {     // rowptr + dinv
    int i = blockIdx.x * blockDim.x + threadIdx.x;
    if (i >= n) return;
    int deg = g_indeg[i];
    int off = g_boff[i >> 8];
    g_rowptr[i] = g_scan[i] - deg + off;
    if (i == n - 1) g_rowptr[n] = g_scan[i] + off;
    g_dinv[i] = rsqrtf((float)(deg + 1));
}

__global__ void k_fill(const int* __restrict__ src, const int* __restrict__ dst, int E) {
    int e = blockIdx.x * blockDim.x + threadIdx.x;
    if (e >= E) return;
    int s = src[e], d = dst[e];
    int pos = g_rowptr[d] + atomicAdd(&g_cursor[d], 1);
    float nm = g_dinv[s] * g_dinv[d];
    g_emeta[pos] = ((ull)__float_as_uint(nm) << 32) | (unsigned)s;
}

// ---------------- GEMM1: h1 = x @ W1  (K=256, 128 cols) --------------------
// 64 rows x 128 cols per block. X tile stored TRANSPOSED so a row-pair is a
// packed f32x2 LDS.64; inner loop = 16 FFMA2 (fma.rn.f32x2) per k.

__global__ void __launch_bounds__(256) k_gemm1(const float* __restrict__ X,
                                               const float* __restrict__ W,
                                               int n) {
    __shared__ float XsT[64][64];    // [k][row]
    __shared__ float Ws [64][128];   // [k][col]
    const int tid  = threadIdx.x;
    const int tcol = tid & 31;       // cols 4*tcol..+3
    const int trow = tid >> 5;       // rows 8*trow..+7
    const int row0 = blockIdx.x * 64;
    const int rbase = trow << 3;

    ull acc[4][4];                   // [rowpair][col], f32x2 packs rows (2rp, 2rp+1)
#pragma unroll
    for (int rp = 0; rp < 4; rp++)
#pragma unroll
        for (int c = 0; c < 4; c++) acc[rp][c] = 0ull;

    for (int k0 = 0; k0 < 256; k0 += 64) {
        // stage X transposed: lane-major rows -> conflict-free STS
#pragma unroll
        for (int i = tid; i < 1024; i += 256) {
            int r = i & 63, c = (i >> 6) << 2;
            int gr = row0 + r;
            float4 v = make_float4(0.f, 0.f, 0.f, 0.f);
            if (gr < n) v = *(const float4*)(X + (size_t)gr * 256 + k0 + c);
            XsT[c + 0][r] = v.x;
            XsT[c + 1][r] = v.y;
            XsT[c + 2][r] = v.z;
            XsT[c + 3][r] = v.w;
        }
#pragma unroll
        for (int i = tid; i < 2048; i += 256) {
            int r = i >> 5, c = (i & 31) << 2;
            *(float4*)&Ws[r][c] = *(const float4*)(W + (k0 + r) * 128 + c);
        }
        __syncthreads();

#pragma unroll 8
        for (int kk = 0; kk < 64; kk++) {
            float4 wq = *(float4*)&Ws[kk][tcol << 2];       // per-lane, conflict-free
            ull wd0 = dup2(wq.x), wd1 = dup2(wq.y), wd2 = dup2(wq.z), wd3 = dup2(wq.w);
            ull x0 = *(const ull*)&XsT[kk][rbase + 0];      // warp-uniform broadcast
            ull x1 = *(const ull*)&XsT[kk][rbase + 2];
            ull x2 = *(const ull*)&XsT[kk][rbase + 4];
            ull x3 = *(const ull*)&XsT[kk][rbase + 6];
            fma2(acc[0][0], x0, wd0); fma2(acc[0][1], x0, wd1);
            fma2(acc[0][2], x0, wd2); fma2(acc[0][3], x0, wd3);
            fma2(acc[1][0], x1, wd0); fma2(acc[1][1], x1, wd1);
            fma2(acc[1][2], x1, wd2); fma2(acc[1][3], x1, wd3);
            fma2(acc[2][0], x2, wd0); fma2(acc[2][1], x2, wd1);
            fma2(acc[2][2], x2, wd2); fma2(acc[2][3], x2, wd3);
            fma2(acc[3][0], x3, wd0); fma2(acc[3][1], x3, wd1);
            fma2(acc[3][2], x3, wd2); fma2(acc[3][3], x3, wd3);
        }
        __syncthreads();
    }

#pragma unroll
    for (int rp = 0; rp < 4; rp++) {
        int gr = row0 + rbase + rp * 2;
        if (gr < n) {
            float4 o0 = make_float4(f2lo(acc[rp][0]), f2lo(acc[rp][1]),
                                    f2lo(acc[rp][2]), f2lo(acc[rp][3]));
            *(float4*)(g_h1 + (size_t)gr * 128 + (tcol << 2)) = o0;
        }
        if (gr + 1 < n) {
            float4 o1 = make_float4(f2hi(acc[rp][0]), f2hi(acc[rp][1]),
                                    f2hi(acc[rp][2]), f2hi(acc[rp][3]));
            *(float4*)(g_h1 + (size_t)(gr + 1) * 128 + (tcol << 2)) = o1;
        }
    }
}

// ---------------- gather layer 1 (warp per node, 2-deep pipeline) ----------

__global__ void __launch_bounds__(256) k_gather1(const float* __restrict__ b1, int n) {
    int node = (blockIdx.x * 256 + threadIdx.x) >> 5;
    int lane = threadIdx.x & 31;
    if (node >= n) return;
    int c = lane << 2;

    float di  = g_dinv[node];
    float di2 = di * di;
    float4 h  = *(const float4*)(g_h1 + (size_t)node * 128 + c);
    float4 a;
    a.x = di2 * h.x; a.y = di2 * h.y; a.z = di2 * h.z; a.w = di2 * h.w;

    int beg = g_rowptr[node], end = g_rowptr[node + 1];
    if (beg < end) {
        ull m0 = g_emeta[beg];
        float4 v0 = *(const float4*)(g_h1 + (size_t)(unsigned)(unsigned)m0 * 128 + c);
        for (int e = beg + 1; e < end; e++) {
            ull m1 = g_emeta[e];                                   // prefetch meta
            float4 v1 = *(const float4*)(g_h1 + (size_t)(unsigned)m1 * 128 + c); // prefetch data
            float nm = __uint_as_float((unsigned)(m0 >> 32));
            a.x += nm * v0.x; a.y += nm * v0.y; a.z += nm * v0.z; a.w += nm * v0.w;
            m0 = m1; v0 = v1;
        }
        float nm = __uint_as_float((unsigned)(m0 >> 32));
        a.x += nm * v0.x; a.y += nm * v0.y; a.z += nm * v0.z; a.w += nm * v0.w;
    }
    float4 b = *(const float4*)(b1 + c);
    float4 o;
    o.x = fmaxf(a.x + b.x, 0.f);
    o.y = fmaxf(a.y + b.y, 0.f);
    o.z = fmaxf(a.z + b.z, 0.f);
    o.w = fmaxf(a.w + b.w, 0.f);
    *(float4*)(g_hid + (size_t)node * 128 + c) = o;
}

// ---------------- GEMM2: h2 = hid @ W2  (K=128, 16 cols) -------------------

__global__ void __launch_bounds__(256) k_gemm2(const float* __restrict__ W2, int n) {
    __shared__ float Xs[64][132];
    __shared__ float Ws[128 * 16];
    const int tid  = threadIdx.x;
    const int row0 = blockIdx.x * 64;

#pragma unroll
    for (int i = tid; i < 512; i += 256)
        ((float4*)Ws)[i] = ((const float4*)W2)[i];

#pragma unroll
    for (int i = tid; i < 64 * 32; i += 256) {
        int r = i >> 5, c = (i & 31) << 2;
        int gr = row0 + r;
        float4 v = make_float4(0.f, 0.f, 0.f, 0.f);
        if (gr < n) v = *(const float4*)(g_hid + (size_t)gr * 128 + c);
        *(float4*)&Xs[r][c] = v;
    }
    __syncthreads();

    const int tcol = tid & 3;
    const int trow = tid >> 2;
    float acc[4] = {0.f, 0.f, 0.f, 0.f};
#pragma unroll 8
    for (int k = 0; k < 128; k++) {
        float  xv = Xs[trow][k];
        float4 wv = *(float4*)&Ws[k * 16 + (tcol << 2)];
        acc[0] += xv * wv.x;
        acc[1] += xv * wv.y;
        acc[2] += xv * wv.z;
        acc[3] += xv * wv.w;
    }
    int gr = row0 + trow;
    if (gr < n)
        *(float4*)(g_h2 + (size_t)gr * 16 + (tcol << 2)) =
            make_float4(acc[0], acc[1], acc[2], acc[3]);
}

// ---------------- gather layer 2 + log_softmax (4 lanes per node) ----------

__global__ void __launch_bounds__(256) k_gather2(const float* __restrict__ b2,
                                                 float* __restrict__ out, int n) {
    int g    = blockIdx.x * 256 + threadIdx.x;
    int node = g >> 2, q = g & 3;
    if (node >= n) return;
    int c = q << 2;

    float di  = g_dinv[node];
    float di2 = di * di;
    float4 h  = *(const float4*)(g_h2 + (size_t)node * 16 + c);
    float4 a;
    a.x = di2 * h.x; a.y = di2 * h.y; a.z = di2 * h.z; a.w = di2 * h.w;

    int beg = g_rowptr[node], end = g_rowptr[node + 1];
    if (beg < end) {
        ull m0 = g_emeta[beg];
        float4 v0 = *(const float4*)(g_h2 + (size_t)(unsigned)m0 * 16 + c);
        for (int e = beg + 1; e < end; e++) {
            ull m1 = g_emeta[e];
            float4 v1 = *(const float4*)(g_h2 + (size_t)(unsigned)m1 * 16 + c);
            float nm = __uint_as_float((unsigned)(m0 >> 32));
            a.x += nm * v0.x; a.y += nm * v0.y; a.z += nm * v0.z; a.w += nm * v0.w;
            m0 = m1; v0 = v1;
        }
        float nm = __uint_as_float((unsigned)(m0 >> 32));
        a.x += nm * v0.x; a.y += nm * v0.y; a.z += nm * v0.z; a.w += nm * v0.w;
    }
    float4 b = *(const float4*)(b2 + c);
    a.x += b.x; a.y += b.y; a.z += b.z; a.w += b.w;

    // log_softmax across 16 features spread over 4 lanes (groups of 4)
    float m4 = fmaxf(fmaxf(a.x, a.y), fmaxf(a.z, a.w));
    m4 = fmaxf(m4, __shfl_xor_sync(0xffffffffu, m4, 1, 4));
    m4 = fmaxf(m4, __shfl_xor_sync(0xffffffffu, m4, 2, 4));
    float s4 = expf(a.x - m4) + expf(a.y - m4) + expf(a.z - m4) + expf(a.w - m4);
    s4 += __shfl_xor_sync(0xffffffffu, s4, 1, 4);
    s4 += __shfl_xor_sync(0xffffffffu, s4, 2, 4);
    float lse = m4 + logf(s4);

    float4 o;
    o.x = a.x - lse; o.y = a.y - lse; o.z = a.z - lse; o.w = a.w - lse;
    *(float4*)(out + (size_t)node * 16 + c) = o;
}

// ---------------------------------------------------------------------------

extern "C" void kernel_launch(void* const* d_in, const int* in_sizes, int n_in,
                              void* d_out, int out_size) {
    const float* x  = (const float*)d_in[0];
    const int*   ei = (const int*)d_in[1];          // int32 (JAX truncation)
    const float* W1 = (const float*)d_in[2];
    const float* b1 = (const float*)d_in[3];
    const float* W2 = (const float*)d_in[4];
    const float* b2 = (const float*)d_in[5];
    float*       out = (float*)d_out;

    const int n = in_sizes[0] / 256;
    const int E = in_sizes[1] / 2;
    const int* src = ei;
    const int* dst = ei + E;
    const int nb = (n + 255) / 256;

    const int T = 256;
    dim3 b(T);

    // One-time handles (created on the first, non-capturing correctness call).
    static cudaStream_t sCsr = nullptr;
    static cudaEvent_t  eFork = nullptr, eJoin = nullptr;
    if (!sCsr) {
        cudaStreamCreateWithFlags(&sCsr, cudaStreamNonBlocking);
        cudaEventCreateWithFlags(&eFork, cudaEventDisableTiming);
        cudaEventCreateWithFlags(&eJoin, cudaEventDisableTiming);
    }

    // fork: CSR build on side stream, GEMM1 on main stream
    cudaEventRecord(eFork, 0);
    cudaStreamWaitEvent(sCsr, eFork, 0);

    k_init     <<<(n + T - 1) / T, b, 0, sCsr>>>(n);
    k_deg_count<<<(E + T - 1) / T, b, 0, sCsr>>>(dst, E);
    k_scan1    <<<nb, b, 0, sCsr>>>(n);
    k_scan2    <<<1, b, 0, sCsr>>>(nb);
    k_scan3    <<<nb, b, 0, sCsr>>>(n);
    k_fill     <<<(E + T - 1) / T, b, 0, sCsr>>>(src, dst, E);
    cudaEventRecord(eJoin, sCsr);

    k_gemm1<<<(n + 63) / 64, b>>>(x, W1, n);

    // join, then the dependent chain
    cudaStreamWaitEvent(0, eJoin, 0);
    k_gather1<<<(n * 32 + T - 1) / T, b>>>(b1, n);
    k_gemm2  <<<(n + 63) / 64, b>>>(W2, n);
    k_gather2<<<(n * 4 + T - 1) / T, b>>>(b2, out, n);
}

// round 9
// speedup vs baseline: 1.4699x; 1.0075x over previous
#include <cuda_runtime.h>

// ---------------------------------------------------------------------------
// GCN 2-layer forward. CSR aggregation + f32x2 GEMM1 + fused gather1/GEMM2.
//   h1 = x @ W1                              [N,128]   (FFMA2 packed GEMM)
//   hid = relu(A_norm @ h1 + b1)  (in registers/smem only — never global)
//   h2 = hid @ W2                            [N,16]    (fused into gather1)
//   out = log_softmax(A_norm @ h2 + b2)      [N,16]    (CSR gather)
// A_norm edge (s->d) weight = dinv[s]*dinv[d], dinv = rsqrt(1+indeg_dst).
// Self-loop handled analytically as dinv[i]^2 * h[i] inside the gathers.
// edge_index is int32 (JAX x64-disabled truncates the requested int64).
// CSR build runs on a forked side stream, overlapped with GEMM1.
// NOTE: no tcgen05 — harness PTX target is compute_103 (no 'a' features).
// ---------------------------------------------------------------------------

#define NMAX 50000
#define EMAX 800000
typedef unsigned long long ull;

__device__ int   g_indeg [NMAX];
__device__ int   g_cursor[NMAX];
__device__ int   g_rowptr[NMAX + 1];
__device__ int   g_scan  [NMAX];
__device__ int   g_bsum  [256];
__device__ int   g_boff  [256];
__device__ float g_dinv  [NMAX];
__device__ __align__(16) ull   g_emeta[EMAX];        // hi: norm bits, lo: src
__device__ __align__(16) float g_h1   [NMAX * 128];
__device__ __align__(16) float g_h2   [NMAX * 16];

// ---------------- f32x2 helpers --------------------------------------------

__device__ __forceinline__ void fma2(ull& acc, ull a, ull b) {
    asm("fma.rn.f32x2 %0, %1, %2, %0;" : "+l"(acc) : "l"(a), "l"(b));
}
__device__ __forceinline__ ull dup2(float w) {
    ull d; unsigned u = __float_as_uint(w);
    asm("mov.b64 %0, {%1, %1};" : "=l"(d) : "r"(u));
    return d;
}
__device__ __forceinline__ float f2lo(ull v) { return __uint_as_float((unsigned)v); }
__device__ __forceinline__ float f2hi(ull v) { return __uint_as_float((unsigned)(v >> 32)); }

// ---------------- CSR build ------------------------------------------------

__global__ void k_init(int n) {
    int i = blockIdx.x * blockDim.x + threadIdx.x;
    if (i < n) { g_indeg[i] = 0; g_cursor[i] = 0; }
}

__global__ void k_deg_count(const int* __restrict__ dst, int E) {
    int e = blockIdx.x * blockDim.x + threadIdx.x;
    if (e < E) atomicAdd(&g_indeg[dst[e]], 1);
}

// inclusive scan within 256-blocks (warp shuffles, 2 syncs)
__global__ void k_scan1(int n) {
    __shared__ int wsum[8];
    int t = threadIdx.x, i = blockIdx.x * 256 + t;
    int lane = t & 31, w = t >> 5;
    int x = (i < n) ? g_indeg[i] : 0;
#pragma unroll
    for (int o = 1; o < 32; o <<= 1) {
        int y = __shfl_up_sync(0xffffffffu, x, o);
        if (lane >= o) x += y;
    }
    if (lane == 31) wsum[w] = x;
    __syncthreads();
    if (w == 0) {
        int s = (lane < 8) ? wsum[lane] : 0;
#pragma unroll
        for (int o = 1; o < 8; o <<= 1) {
            int y = __shfl_up_sync(0xffffffffu, s, o);
            if (lane >= o) s += y;
        }
        if (lane < 8) wsum[lane] = s;
    }
    __syncthreads();
    if (w > 0) x += wsum[w - 1];
    if (i < n) g_scan[i] = x;
    if (t == 255) g_bsum[blockIdx.x] = x;
}

// exclusive scan of block totals (single block; nb <= 256)
__global__ void k_scan2(int nb) {
    __shared__ int wsum[8];
    int t = threadIdx.x;
    int lane = t & 31, w = t >> 5;
    int v = (t < nb) ? g_bsum[t] : 0;
    int x = v;
#pragma unroll
    for (int o = 1; o < 32; o <<= 1) {
        int y = __shfl_up_sync(0xffffffffu, x, o);
        if (lane >= o) x += y;
    }
    if (lane == 31) wsum[w] = x;
    __syncthreads();
    if (w == 0) {
        int s = (lane < 8) ? wsum[lane] : 0;
#pragma unroll
        for (int o = 1; o < 8; o <<= 1) {
            int y = __shfl_up_sync(0xffffffffu, s, o);
            if (lane >= o) s += y;
        }
        if (lane < 8) wsum[lane] = s;
    }
    __syncthreads();
    if (w > 0) x += wsum[w - 1];
    g_boff[t] = x - v;   // exclusive
}

__global__ void k_scan3(int n) {     // rowptr + dinv
    int i = blockIdx.x * blockDim.x + threadIdx.x;
    if (i >= n) return;
    int deg = g_indeg[i];
    int off = g_boff[i >> 8];
    g_rowptr[i] = g_scan[i] - deg + off;
    if (i == n - 1) g_rowptr[n] = g_scan[i] + off;
    g_dinv[i] = rsqrtf((float)(deg + 1));
}

__global__ void k_fill(const int* __restrict__ src, const int* __restrict__ dst, int E) {
    int e = blockIdx.x * blockDim.x + threadIdx.x;
    if (e >= E) return;
    int s = src[e], d = dst[e];
    int pos = g_rowptr[d] + atomicAdd(&g_cursor[d], 1);
    float nm = g_dinv[s] * g_dinv[d];
    g_emeta[pos] = ((ull)__float_as_uint(nm) << 32) | (unsigned)s;
}

// ---------------- GEMM1: h1 = x @ W1  (K=256, 128 cols) --------------------
// 64 rows x 128 cols per block. X tile stored TRANSPOSED so a row-pair is a
// packed f32x2 LDS.64; inner loop = 16 FFMA2 (fma.rn.f32x2) per k.

__global__ void __launch_bounds__(256) k_gemm1(const float* __restrict__ X,
                                               const float* __restrict__ W,
                                               int n) {
    __shared__ float XsT[64][64];    // [k][row]
    __shared__ float Ws [64][128];   // [k][col]
    const int tid  = threadIdx.x;
    const int tcol = tid & 31;       // cols 4*tcol..+3
    const int trow = tid >> 5;       // rows 8*trow..+7
    const int row0 = blockIdx.x * 64;
    const int rbase = trow << 3;

    ull acc[4][4];                   // [rowpair][col], f32x2 packs rows (2rp, 2rp+1)
#pragma unroll
    for (int rp = 0; rp < 4; rp++)
#pragma unroll
        for (int c = 0; c < 4; c++) acc[rp][c] = 0ull;

    for (int k0 = 0; k0 < 256; k0 += 64) {
        // stage X transposed: lane-major rows -> conflict-free STS
#pragma unroll
        for (int i = tid; i < 1024; i += 256) {
            int r = i & 63, c = (i >> 6) << 2;
            int gr = row0 + r;
            float4 v = make_float4(0.f, 0.f, 0.f, 0.f);
            if (gr < n) v = *(const float4*)(X + (size_t)gr * 256 + k0 + c);
            XsT[c + 0][r] = v.x;
            XsT[c + 1][r] = v.y;
            XsT[c + 2][r] = v.z;
            XsT[c + 3][r] = v.w;
        }
#pragma unroll
        for (int i = tid; i < 2048; i += 256) {
            int r = i >> 5, c = (i & 31) << 2;
            *(float4*)&Ws[r][c] = *(const float4*)(W + (k0 + r) * 128 + c);
        }
        __syncthreads();

#pragma unroll 8
        for (int kk = 0; kk < 64; kk++) {
            float4 wq = *(float4*)&Ws[kk][tcol << 2];       // per-lane, conflict-free
            ull wd0 = dup2(wq.x), wd1 = dup2(wq.y), wd2 = dup2(wq.z), wd3 = dup2(wq.w);
            ull x0 = *(const ull*)&XsT[kk][rbase + 0];      // warp-uniform broadcast
            ull x1 = *(const ull*)&XsT[kk][rbase + 2];
            ull x2 = *(const ull*)&XsT[kk][rbase + 4];
            ull x3 = *(const ull*)&XsT[kk][rbase + 6];
            fma2(acc[0][0], x0, wd0); fma2(acc[0][1], x0, wd1);
            fma2(acc[0][2], x0, wd2); fma2(acc[0][3], x0, wd3);
            fma2(acc[1][0], x1, wd0); fma2(acc[1][1], x1, wd1);
            fma2(acc[1][2], x1, wd2); fma2(acc[1][3], x1, wd3);
            fma2(acc[2][0], x2, wd0); fma2(acc[2][1], x2, wd1);
            fma2(acc[2][2], x2, wd2); fma2(acc[2][3], x2, wd3);
            fma2(acc[3][0], x3, wd0); fma2(acc[3][1], x3, wd1);
            fma2(acc[3][2], x3, wd2); fma2(acc[3][3], x3, wd3);
        }
        __syncthreads();
    }

#pragma unroll
    for (int rp = 0; rp < 4; rp++) {
        int gr = row0 + rbase + rp * 2;
        if (gr < n) {
            float4 o0 = make_float4(f2lo(acc[rp][0]), f2lo(acc[rp][1]),
                                    f2lo(acc[rp][2]), f2lo(acc[rp][3]));
            *(float4*)(g_h1 + (size_t)gr * 128 + (tcol << 2)) = o0;
        }
        if (gr + 1 < n) {
            float4 o1 = make_float4(f2hi(acc[rp][0]), f2hi(acc[rp][1]),
                                    f2hi(acc[rp][2]), f2hi(acc[rp][3]));
            *(float4*)(g_h1 + (size_t)(gr + 1) * 128 + (tcol << 2)) = o1;
        }
    }
}

// ---------------- fused gather1 + GEMM2 (warp per node) --------------------
// Phase A: hid = relu(A_norm @ h1 + b1) into registers (float4/lane).
// Phase B: stage hid to per-warp smem; half-warp computes one of 16 output
//          features over half of K; shfl_down(16) combines; write h2.

__global__ void __launch_bounds__(256) k_gather1_gemm2(const float* __restrict__ b1,
                                                       const float* __restrict__ W2,
                                                       int n) {
    __shared__ float W2s[16][132];        // W2s[j][k] = W2[k][j] (transposed, padded)
    __shared__ float hidS[8][128];        // per-warp hid row
    const int tid  = threadIdx.x;
    const int w    = tid >> 5;
    const int lane = tid & 31;

    // stage W2 transposed (8KB, once per block)
#pragma unroll
    for (int i = tid; i < 2048; i += 256) {
        int k = i >> 4, j = i & 15;
        W2s[j][k] = W2[k * 16 + j];
    }
    __syncthreads();

    int node = blockIdx.x * 8 + w;
    if (node >= n) return;
    int c = lane << 2;

    float di  = g_dinv[node];
    float di2 = di * di;
    float4 h  = *(const float4*)(g_h1 + (size_t)node * 128 + c);
    float4 a;
    a.x = di2 * h.x; a.y = di2 * h.y; a.z = di2 * h.z; a.w = di2 * h.w;

    int beg = g_rowptr[node], end = g_rowptr[node + 1];
    if (beg < end) {
        ull m0 = g_emeta[beg];
        float4 v0 = *(const float4*)(g_h1 + (size_t)(unsigned)m0 * 128 + c);
        for (int e = beg + 1; e < end; e++) {
            ull m1 = g_emeta[e];                                        // prefetch meta
            float4 v1 = *(const float4*)(g_h1 + (size_t)(unsigned)m1 * 128 + c);
            float nm = __uint_as_float((unsigned)(m0 >> 32));
            a.x += nm * v0.x; a.y += nm * v0.y; a.z += nm * v0.z; a.w += nm * v0.w;
            m0 = m1; v0 = v1;
        }
        float nm = __uint_as_float((unsigned)(m0 >> 32));
        a.x += nm * v0.x; a.y += nm * v0.y; a.z += nm * v0.z; a.w += nm * v0.w;
    }
    float4 b = *(const float4*)(b1 + c);
    float4 o;
    o.x = fmaxf(a.x + b.x, 0.f);
    o.y = fmaxf(a.y + b.y, 0.f);
    o.z = fmaxf(a.z + b.z, 0.f);
    o.w = fmaxf(a.w + b.w, 0.f);

    // Phase B: hid row -> smem, per-warp GEMM2
    *(float4*)&hidS[w][c] = o;
    __syncwarp();

    const int j  = lane & 15;             // output feature
    const int k0 = (lane >> 4) << 6;      // 0 or 64 (half of K)
    float acc = 0.f;
#pragma unroll
    for (int kk = 0; kk < 64; kk += 4) {
        float4 hv = *(float4*)&hidS[w][k0 + kk];       // 2-addr broadcast
        float4 wv = *(float4*)&W2s[j][k0 + kk];
        acc += hv.x * wv.x + hv.y * wv.y + hv.z * wv.z + hv.w * wv.w;
    }
    acc += __shfl_down_sync(0xffffffffu, acc, 16);
    if (lane < 16) g_h2[(size_t)node * 16 + j] = acc;
}

// ---------------- gather layer 2 + log_softmax (4 lanes per node) ----------

__global__ void __launch_bounds__(256) k_gather2(const float* __restrict__ b2,
                                                 float* __restrict__ out, int n) {
    int g    = blockIdx.x * 256 + threadIdx.x;
    int node = g >> 2, q = g & 3;
    if (node >= n) return;
    int c = q << 2;

    float di  = g_dinv[node];
    float di2 = di * di;
    float4 h  = *(const float4*)(g_h2 + (size_t)node * 16 + c);
    float4 a;
    a.x = di2 * h.x; a.y = di2 * h.y; a.z = di2 * h.z; a.w = di2 * h.w;

    int beg = g_rowptr[node], end = g_rowptr[node + 1];
    if (beg < end) {
        ull m0 = g_emeta[beg];
        float4 v0 = *(const float4*)(g_h2 + (size_t)(unsigned)m0 * 16 + c);
        for (int e = beg + 1; e < end; e++) {
            ull m1 = g_emeta[e];
            float4 v1 = *(const float4*)(g_h2 + (size_t)(unsigned)m1 * 16 + c);
            float nm = __uint_as_float((unsigned)(m0 >> 32));
            a.x += nm * v0.x; a.y += nm * v0.y; a.z += nm * v0.z; a.w += nm * v0.w;
            m0 = m1; v0 = v1;
        }
        float nm = __uint_as_float((unsigned)(m0 >> 32));
        a.x += nm * v0.x; a.y += nm * v0.y; a.z += nm * v0.z; a.w += nm * v0.w;
    }
    float4 b = *(const float4*)(b2 + c);
    a.x += b.x; a.y += b.y; a.z += b.z; a.w += b.w;

    // log_softmax across 16 features spread over 4 lanes (groups of 4)
    float m4 = fmaxf(fmaxf(a.x, a.y), fmaxf(a.z, a.w));
    m4 = fmaxf(m4, __shfl_xor_sync(0xffffffffu, m4, 1, 4));
    m4 = fmaxf(m4, __shfl_xor_sync(0xffffffffu, m4, 2, 4));
    float s4 = expf(a.x - m4) + expf(a.y - m4) + expf(a.z - m4) + expf(a.w - m4);
    s4 += __shfl_xor_sync(0xffffffffu, s4, 1, 4);
    s4 += __shfl_xor_sync(0xffffffffu, s4, 2, 4);
    float lse = m4 + logf(s4);

    float4 o;
    o.x = a.x - lse; o.y = a.y - lse; o.z = a.z - lse; o.w = a.w - lse;
    *(float4*)(out + (size_t)node * 16 + c) = o;
}

// ---------------------------------------------------------------------------

extern "C" void kernel_launch(void* const* d_in, const int* in_sizes, int n_in,
                              void* d_out, int out_size) {
    const float* x  = (const float*)d_in[0];
    const int*   ei = (const int*)d_in[1];          // int32 (JAX truncation)
    const float* W1 = (const float*)d_in[2];
    const float* b1 = (const float*)d_in[3];
    const float* W2 = (const float*)d_in[4];
    const float* b2 = (const float*)d_in[5];
    float*       out = (float*)d_out;

    const int n = in_sizes[0] / 256;
    const int E = in_sizes[1] / 2;
    const int* src = ei;
    const int* dst = ei + E;
    const int nb = (n + 255) / 256;

    const int T = 256;
    dim3 b(T);

    // One-time handles (created on the first, non-capturing correctness call).
    static cudaStream_t sCsr = nullptr;
    static cudaEvent_t  eFork = nullptr, eJoin = nullptr;
    if (!sCsr) {
        cudaStreamCreateWithFlags(&sCsr, cudaStreamNonBlocking);
        cudaEventCreateWithFlags(&eFork, cudaEventDisableTiming);
        cudaEventCreateWithFlags(&eJoin, cudaEventDisableTiming);
    }

    // fork: CSR build on side stream, GEMM1 on main stream
    cudaEventRecord(eFork, 0);
    cudaStreamWaitEvent(sCsr, eFork, 0);

    k_init     <<<(n + T - 1) / T, b, 0, sCsr>>>(n);
    k_deg_count<<<(E + T - 1) / T, b, 0, sCsr>>>(dst, E);
    k_scan1    <<<nb, b, 0, sCsr>>>(n);
    k_scan2    <<<1, b, 0, sCsr>>>(nb);
    k_scan3    <<<nb, b, 0, sCsr>>>(n);
    k_fill     <<<(E + T - 1) / T, b, 0, sCsr>>>(src, dst, E);
    cudaEventRecord(eJoin, sCsr);

    k_gemm1<<<(n + 63) / 64, b>>>(x, W1, n);

    // join, then the dependent chain
    cudaStreamWaitEvent(0, eJoin, 0);
    k_gather1_gemm2<<<(n + 7) / 8, b>>>(b1, W2, n);
    k_gather2<<<(n * 4 + T - 1) / T, b>>>(b2, out, n);
}